// round 15
// baseline (speedup 1.0000x reference)
#include <cuda_runtime.h>
#include <cuda_fp16.h>

#define D 64
#define L 64
#define BB 8
#define MAT (D*D)          // 4096 elems per matrix
#define NMAT (BB*L)        // 512 matrices
#define PAH 72             // fp16 A pitch (halves) -> 144B rows, conflict-free
#define PK_GRID 740        // 148 SMs x 5 resident CTAs

// All matrices in reciprocal-exp domain: W = exp(-m), stored fp16 normalized
// per-quarter (max=1) with float scales. log-semiring matmul:
//   out[i,j] = rcp( sum_k rcp( A[i,k] + B[k,j] ) )   (scale-homogeneous)
__device__ float g_p0tab[MAT];         // exp(-p[0]) fp32 (final)
__device__ int   g_ctr[4];             // per-pass persistent work counters

// fp16 normalized storage (+ per-quarter float4 scales)
__device__ uint4 h_buf0_[NMAT * MAT / 8];
__device__ uint4 h_buf1_[NMAT * MAT / 8];
__device__ uint4 h_qtab_[256 * MAT / 8];
__device__ uint4 h_ttab_[16 * MAT / 8];
__device__ uint4 h_wtab_[4 * MAT / 8];
__device__ float4 g_sc0[NMAT];
__device__ float4 g_sc1[NMAT];
__device__ float4 g_scq[256];
__device__ float4 g_sct[16];
__device__ float4 g_scw[4];
#define H_BUF0 ((__half*)h_buf0_)
#define H_BUF1 ((__half*)h_buf1_)
#define H_QTAB ((__half*)h_qtab_)
#define H_TTAB ((__half*)h_ttab_)
#define H_WTAB ((__half*)h_wtab_)

__device__ __forceinline__ float frcp(float x) {
    float r;
    asm("rcp.approx.f32 %0, %1;" : "=f"(r) : "f"(x));
    return r;
}

// cp.async helpers
__device__ __forceinline__ unsigned smem_u32(const void* p) {
    return (unsigned)__cvta_generic_to_shared(p);
}
#define CPA16(s, g) asm volatile("cp.async.ca.shared.global [%0], [%1], 16;" \
                                 :: "r"(s), "l"(g) : "memory")
#define CPA_COMMIT() asm volatile("cp.async.commit_group;" ::: "memory")
#define CPA_WAIT1()  asm volatile("cp.async.wait_group 1;" ::: "memory")

// Packed fp16x2 reciprocal WITHOUT MUFU: 16-bit magic estimate (lanes in
// [0,2] -- normalization guarantees no cross-lane borrow) + ONE Halley step
// (cubic): residual e0^3 ~ 4e-5 < fp16 eps. x=0 -> inf (correct limit).
__device__ __forceinline__ __half2 h2rcp_nr(__half2 x) {
    unsigned xi = *reinterpret_cast<unsigned*>(&x);
    unsigned yi = 0x77847784u - xi;
    __half2 y = *reinterpret_cast<__half2*>(&yi);
    const __half2 one = __float2half2_rn(1.f);
    __half2 nx = __hneg2(x);
    __half2 e = __hfma2(nx, y, one);         // e = 1 - x*y
    __half2 t = __hfma2(e, e, e);            // t = e + e^2
    y = __hfma2(y, t, y);                    // y *= 1 + e + e^2
    return y;
}

__device__ __forceinline__ float sc_comp(float4 s, int q) {
    return (q < 2) ? (q == 0 ? s.x : s.y) : (q == 2 ? s.z : s.w);
}

__device__ __forceinline__ int quad_idx(const int* __restrict__ act, int b, int m) {
    const int* a = act + b * L + (m - 3);
    return ((a[0] * 4 + a[1]) * 4 + a[2]) * 4 + a[3];
}

// Pointer-only resolver (for prefetch)
__device__ __forceinline__ const __half* latest_ptr(const int* __restrict__ act,
                                                    int b, int m, int slog) {
    int slot = b * L + m;
    size_t off = (size_t)slot * MAT;
    if (m < 2) return H_BUF0 + off;
    int p = 31 - __clz(m);
    if (p > slog - 1) p = slog - 1;
    if (p == 1) {
        if (m == 2) return H_BUF1 + off;
        return H_QTAB + (size_t)quad_idx(act, b, m) * MAT;
    }
    return (p & 1) ? H_BUF1 + off : H_BUF0 + off;
}

__device__ __forceinline__ float4 latest_sc(const int* __restrict__ act,
                                            int b, int m, int slog) {
    int slot = b * L + m;
    if (m < 2) return g_sc0[slot];
    int p = 31 - __clz(m);
    if (p > slog - 1) p = slog - 1;
    if (p == 1) {
        if (m == 2) return g_sc1[slot];
        return g_scq[quad_idx(act, b, m)];
    }
    return (p & 1) ? g_sc1[slot] : g_sc0[slot];
}

struct HMat { const __half* m; float4 sc; };
__device__ __forceinline__ HMat latest_h(const int* __restrict__ act,
                                         int b, int m, int slog) {
    HMat r;
    r.m = latest_ptr(act, b, m, slog);
    r.sc = latest_sc(act, b, m, slog);
    return r;
}

// ---------------------------------------------------------------------------
// fp16 quarter matmul (staging version, used by pairh/stage2h).
// ---------------------------------------------------------------------------
__device__ __forceinline__ void hmm_quarter(const __half* __restrict__ Ah, float4 scA,
                                            const __half* __restrict__ Bh, float scB,
                                            __half* __restrict__ Dst,
                                            float* __restrict__ scOut, int q) {
    __shared__ __align__(16) __half sA[D * PAH];
    __shared__ __align__(16) __half sB[D * 16];
    __shared__ float wred[8];
    const int t = threadIdx.x;

    float s = fmaxf(fmaxf(fmaxf(scA.x, scA.y), fmaxf(scA.z, scA.w)), scB);
    float invs = 1.f / s;
    __half2 rB = __float2half2_rn(scB * invs);

#pragma unroll
    for (int i = 0; i < 2; i++) {
        int id = t + i * 256;
        int r = id >> 3, c8 = id & 7;
        __half2 rA = __float2half2_rn(sc_comp(scA, c8 >> 1) * invs);
        uint4 v = ((const uint4*)Ah)[id];
        __half2* hv = (__half2*)&v;
        hv[0] = __hmul2(hv[0], rA); hv[1] = __hmul2(hv[1], rA);
        hv[2] = __hmul2(hv[2], rA); hv[3] = __hmul2(hv[3], rA);
        *(uint4*)&sA[r * PAH + c8 * 8] = v;
    }
    if (t < 128) {
        int r = t >> 1, c8 = t & 1;
        uint4 v = *(const uint4*)&Bh[r * D + q * 16 + c8 * 8];
        __half2* hv = (__half2*)&v;
        hv[0] = __hmul2(hv[0], rB); hv[1] = __hmul2(hv[1], rB);
        hv[2] = __hmul2(hv[2], rB); hv[3] = __hmul2(hv[3], rB);
        *(uint4*)&sB[r * 16 + c8 * 8] = v;
    }
    __syncthreads();

    const int row = t >> 2, cg = t & 3;
    const __half* ap = &sA[row * PAH];
    const __half* bp = &sB[cg * 4];
    const __half2 hz = __float2half2_rn(0.f);
    __half2 acc01[8], acc23[8];
#pragma unroll
    for (int i = 0; i < 8; i++) { acc01[i] = hz; acc23[i] = hz; }

#pragma unroll
    for (int k8 = 0; k8 < 8; k8++) {
        uint4 a8 = *(const uint4*)&ap[k8 * 8];
        const __half2* ah = (const __half2*)&a8;
#pragma unroll
        for (int kk = 0; kk < 4; kk++) {
            int k0 = k8 * 8 + kk * 2;
            __half2 alo = __low2half2(ah[kk]);
            __half2 ahi = __high2half2(ah[kk]);
            int pi = kk * 2;
            uint2 b0 = *(const uint2*)&bp[k0 * 16];
            __half2 b01 = *(__half2*)&b0.x, b23 = *(__half2*)&b0.y;
            acc01[pi] = __hadd2(acc01[pi], h2rcp_nr(__hadd2(alo, b01)));
            acc23[pi] = __hadd2(acc23[pi], h2rcp_nr(__hadd2(alo, b23)));
            uint2 b1 = *(const uint2*)&bp[(k0 + 1) * 16];
            __half2 c01 = *(__half2*)&b1.x, c23 = *(__half2*)&b1.y;
            acc01[pi + 1] = __hadd2(acc01[pi + 1], h2rcp_nr(__hadd2(ahi, c01)));
            acc23[pi + 1] = __hadd2(acc23[pi + 1], h2rcp_nr(__hadd2(ahi, c23)));
        }
    }

    float s0 = 0.f, s1 = 0.f, s2 = 0.f, s3 = 0.f;
#pragma unroll
    for (int i = 0; i < 8; i++) {
        float2 f01 = __half22float2(acc01[i]);
        float2 f23 = __half22float2(acc23[i]);
        s0 += f01.x; s1 += f01.y; s2 += f23.x; s3 += f23.y;
    }
    float o0 = frcp(s0), o1 = frcp(s1), o2 = frcp(s2), o3 = frcp(s3);

    float m = fmaxf(fmaxf(o0, o1), fmaxf(o2, o3));
#pragma unroll
    for (int off = 16; off; off >>= 1)
        m = fmaxf(m, __shfl_xor_sync(0xffffffffu, m, off));
    if ((t & 31) == 0) wred[t >> 5] = m;
    __syncthreads();
    float mx = wred[0];
#pragma unroll
    for (int i = 1; i < 8; i++) mx = fmaxf(mx, wred[i]);
    float inv = (mx > 0.f) ? frcp(mx) : 0.f;

    __half2 h0 = __floats2half2_rn(o0 * inv, o1 * inv);
    __half2 h1 = __floats2half2_rn(o2 * inv, o3 * inv);
    uint2 u;
    u.x = *(unsigned*)&h0;
    u.y = *(unsigned*)&h1;
    *(uint2*)&Dst[row * D + q * 16 + cg * 4] = u;
    if (t == 0) *scOut = s * mx;
}

// ---------------------------------------------------------------------------
// Persistent doubling pass: atomic job queue + cp.async double-buffered tiles.
// Job = (matrix index, quarter q). No intra-pass dependencies.
// ---------------------------------------------------------------------------
__device__ __forceinline__ void pk_prefetch(const int* __restrict__ act,
                                            int j, int njobs, int step, int n,
                                            int slog, __half* sAbuf,
                                            __half* sBbuf, int t) {
    if (j >= njobs) return;
    int idx = j >> 2, q = j & 3;
    int b = idx / n;
    int l = step + (idx - b * n);
    const __half* Ap = latest_ptr(act, b, l - step, slog);
    const __half* Bp = latest_ptr(act, b, l, slog);
    {
        int r = t >> 3, c8 = t & 7;
        CPA16(smem_u32(&sAbuf[r * PAH + c8 * 8]), Ap + r * D + c8 * 8);
        int id = t + 256;
        r = id >> 3; c8 = id & 7;
        CPA16(smem_u32(&sAbuf[r * PAH + c8 * 8]), Ap + r * D + c8 * 8);
    }
    if (t < 128) {
        int r = t >> 1, c8 = t & 1;
        CPA16(smem_u32(&sBbuf[r * 16 + c8 * 8]), Bp + r * D + q * 16 + c8 * 8);
    }
}

__global__ void __launch_bounds__(256, 5) hstep_pk(const int* __restrict__ act,
                                                   int slog, int njobs) {
    __shared__ __align__(16) __half sA[2][D * PAH];
    __shared__ __align__(16) __half sB[2][D * 16];
    __shared__ float wred[8];
    __shared__ int sjid[2];
    const int t = threadIdx.x;
    const int step = 1 << slog, n = L - step;
    int* ctr = &g_ctr[slog - 2];

    if (t == 0) sjid[0] = atomicAdd(ctr, 1);
    __syncthreads();
    int jid = sjid[0];
    int cur = 0;

    pk_prefetch(act, jid, njobs, step, n, slog, sA[0], sB[0], t);
    CPA_COMMIT();

    while (jid < njobs) {
        if (t == 0) sjid[cur ^ 1] = atomicAdd(ctr, 1);
        __syncthreads();                               // (a)
        int jnext = sjid[cur ^ 1];
        pk_prefetch(act, jnext, njobs, step, n, slog, sA[cur ^ 1], sB[cur ^ 1], t);
        CPA_COMMIT();
        CPA_WAIT1();
        __syncthreads();                               // (b) buf[cur] ready

        // full decode of current job
        int idx = jid >> 2, q = jid & 3;
        int b = idx / n;
        int l = step + (idx - b * n);
        float4 scA = latest_sc(act, b, l - step, slog);
        float scB = sc_comp(latest_sc(act, b, l, slog), q);
        float s = fmaxf(fmaxf(fmaxf(scA.x, scA.y), fmaxf(scA.z, scA.w)), scB);
        float invs = 1.f / s;

        // in-place rescale of the smaller operand(s) to the common scale
        {
            __half2 rB = __float2half2_rn(scB * invs);
#pragma unroll
            for (int i = 0; i < 2; i++) {
                int id = t + i * 256;
                int r = id >> 3, c8 = id & 7;
                __half2 rr = __float2half2_rn(sc_comp(scA, c8 >> 1) * invs);
                uint4 v = *(uint4*)&sA[cur][r * PAH + c8 * 8];
                __half2* hv = (__half2*)&v;
                hv[0] = __hmul2(hv[0], rr); hv[1] = __hmul2(hv[1], rr);
                hv[2] = __hmul2(hv[2], rr); hv[3] = __hmul2(hv[3], rr);
                *(uint4*)&sA[cur][r * PAH + c8 * 8] = v;
            }
            if (t < 128) {
                int r = t >> 1, c8 = t & 1;
                uint4 v = *(uint4*)&sB[cur][r * 16 + c8 * 8];
                __half2* hv = (__half2*)&v;
                hv[0] = __hmul2(hv[0], rB); hv[1] = __hmul2(hv[1], rB);
                hv[2] = __hmul2(hv[2], rB); hv[3] = __hmul2(hv[3], rB);
                *(uint4*)&sB[cur][r * 16 + c8 * 8] = v;
            }
        }
        __syncthreads();                               // (c)

        // compute (identical math to staged version)
        const int row = t >> 2, cg = t & 3;
        const __half* ap = &sA[cur][row * PAH];
        const __half* bp = &sB[cur][cg * 4];
        const __half2 hz = __float2half2_rn(0.f);
        __half2 acc01[8], acc23[8];
#pragma unroll
        for (int i = 0; i < 8; i++) { acc01[i] = hz; acc23[i] = hz; }

#pragma unroll
        for (int k8 = 0; k8 < 8; k8++) {
            uint4 a8 = *(const uint4*)&ap[k8 * 8];
            const __half2* ah = (const __half2*)&a8;
#pragma unroll
            for (int kk = 0; kk < 4; kk++) {
                int k0 = k8 * 8 + kk * 2;
                __half2 alo = __low2half2(ah[kk]);
                __half2 ahi = __high2half2(ah[kk]);
                int pi = kk * 2;
                uint2 b0 = *(const uint2*)&bp[k0 * 16];
                __half2 b01 = *(__half2*)&b0.x, b23 = *(__half2*)&b0.y;
                acc01[pi] = __hadd2(acc01[pi], h2rcp_nr(__hadd2(alo, b01)));
                acc23[pi] = __hadd2(acc23[pi], h2rcp_nr(__hadd2(alo, b23)));
                uint2 b1 = *(const uint2*)&bp[(k0 + 1) * 16];
                __half2 c01 = *(__half2*)&b1.x, c23 = *(__half2*)&b1.y;
                acc01[pi + 1] = __hadd2(acc01[pi + 1], h2rcp_nr(__hadd2(ahi, c01)));
                acc23[pi + 1] = __hadd2(acc23[pi + 1], h2rcp_nr(__hadd2(ahi, c23)));
            }
        }

        float s0 = 0.f, s1 = 0.f, s2 = 0.f, s3 = 0.f;
#pragma unroll
        for (int i = 0; i < 8; i++) {
            float2 f01 = __half22float2(acc01[i]);
            float2 f23 = __half22float2(acc23[i]);
            s0 += f01.x; s1 += f01.y; s2 += f23.x; s3 += f23.y;
        }
        float o0 = frcp(s0), o1 = frcp(s1), o2 = frcp(s2), o3 = frcp(s3);

        float m = fmaxf(fmaxf(o0, o1), fmaxf(o2, o3));
#pragma unroll
        for (int off = 16; off; off >>= 1)
            m = fmaxf(m, __shfl_xor_sync(0xffffffffu, m, off));
        if ((t & 31) == 0) wred[t >> 5] = m;
        __syncthreads();
        float mx = wred[0];
#pragma unroll
        for (int i = 1; i < 8; i++) mx = fmaxf(mx, wred[i]);
        float inv = (mx > 0.f) ? frcp(mx) : 0.f;

        int slot = b * L + l;
        __half* dst = ((slog & 1) ? H_BUF1 : H_BUF0) + (size_t)slot * MAT;
        __half2 h0 = __floats2half2_rn(o0 * inv, o1 * inv);
        __half2 h1 = __floats2half2_rn(o2 * inv, o3 * inv);
        uint2 u;
        u.x = *(unsigned*)&h0;
        u.y = *(unsigned*)&h1;
        *(uint2*)&dst[row * D + q * 16 + cg * 4] = u;
        if (t == 0)
            *((float*)(((slog & 1) ? g_sc1 : g_sc0) + slot) + q) = s * mx;

        cur ^= 1;
        jid = jnext;
    }
}

// ---------------------------------------------------------------------------
// exp tables: a==0 -> p0tab fp32 (+ counter reset). a>=1 -> wtab fp16 + scale.
// ---------------------------------------------------------------------------
__global__ void exp_tab_kernel(const float* __restrict__ p) {
    int a = blockIdx.x;
    __shared__ float wred[8];
    int t = threadIdx.x;  // 256
    if (a == 0 && t == 0) {
        g_ctr[0] = 0; g_ctr[1] = 0; g_ctr[2] = 0; g_ctr[3] = 0;
    }
    const float4* src = (const float4*)(p + (size_t)a * MAT);
    float4 v[4];
    float m = 0.f;
#pragma unroll
    for (int i = 0; i < 4; i++) {
        float4 x = src[t + i * 256];
        v[i] = make_float4(expf(-x.x), expf(-x.y), expf(-x.z), expf(-x.w));
        m = fmaxf(m, fmaxf(fmaxf(v[i].x, v[i].y), fmaxf(v[i].z, v[i].w)));
    }
    if (a == 0) {
#pragma unroll
        for (int i = 0; i < 4; i++) ((float4*)g_p0tab)[t + i * 256] = v[i];
        return;
    }
#pragma unroll
    for (int off = 16; off; off >>= 1)
        m = fmaxf(m, __shfl_xor_sync(0xffffffffu, m, off));
    if ((t & 31) == 0) wred[t >> 5] = m;
    __syncthreads();
    float mx = wred[0];
#pragma unroll
    for (int i = 1; i < 8; i++) mx = fmaxf(mx, wred[i]);
    float inv = (mx > 0.f) ? 1.f / mx : 0.f;
    __half* hdst = H_WTAB + (size_t)(a - 1) * MAT;
#pragma unroll
    for (int i = 0; i < 4; i++) {
        __half2 h0 = __floats2half2_rn(v[i].x * inv, v[i].y * inv);
        __half2 h1 = __floats2half2_rn(v[i].z * inv, v[i].w * inv);
        uint2 u; u.x = *(unsigned*)&h0; u.y = *(unsigned*)&h1;
        ((uint2*)hdst)[t + i * 256] = u;
    }
    if (t == 0) g_scw[a - 1] = make_float4(mx, mx, mx, mx);
}

// pair products fp16: 16 pairs x 4 quarters = 64 CTAs
__global__ void __launch_bounds__(256, 6) pairh_kernel() {
    int pidx = blockIdx.x >> 2, q = blockIdx.x & 3;
    int a = pidx >> 2, b = pidx & 3;
    hmm_quarter(H_WTAB + (size_t)a * MAT, g_scw[a],
                H_WTAB + (size_t)b * MAT, sc_comp(g_scw[b], q),
                H_TTAB + (size_t)pidx * MAT, (float*)&g_sct[pidx] + q, q);
}

// quads (1024) + tris (32) + base fp16 copies l=0,1 (16) = 1072 CTAs
__global__ void __launch_bounds__(256, 6) stage2h_kernel(const int* __restrict__ act) {
    int bid = blockIdx.x;
    if (bid < 1024) {
        int qidx = bid >> 2, q = bid & 3;
        int hi = qidx >> 4, lo = qidx & 15;
        hmm_quarter(H_TTAB + (size_t)hi * MAT, g_sct[hi],
                    H_TTAB + (size_t)lo * MAT, sc_comp(g_sct[lo], q),
                    H_QTAB + (size_t)qidx * MAT, (float*)&g_scq[qidx] + q, q);
    } else if (bid < 1056) {
        int i = bid - 1024;
        int b = i >> 2, q = i & 3;
        int a0 = act[b * L], a12 = act[b * L + 1] * 4 + act[b * L + 2];
        int slot = b * L + 2;
        hmm_quarter(H_WTAB + (size_t)a0 * MAT, g_scw[a0],
                    H_TTAB + (size_t)a12 * MAT, sc_comp(g_sct[a12], q),
                    H_BUF1 + (size_t)slot * MAT, (float*)&g_sc1[slot] + q, q);
    } else {
        int i = bid - 1056;                 // 0..15
        int b = i >> 1, which = i & 1;      // l = 0 or 1
        int slot = b * L + which;
        const uint4* src;
        float4 sc;
        if (which) {
            int pidx = act[b * L] * 4 + act[b * L + 1];
            src = (const uint4*)(H_TTAB + (size_t)pidx * MAT);
            sc = g_sct[pidx];
        } else {
            int a0 = act[b * L];
            src = (const uint4*)(H_WTAB + (size_t)a0 * MAT);
            sc = g_scw[a0];
        }
        uint4* dst = (uint4*)(H_BUF0 + (size_t)slot * MAT);
        for (int j = threadIdx.x; j < MAT / 8; j += 256) dst[j] = src[j];
        if (threadIdx.x == 0) g_sc0[slot] = sc;
    }
}

// Final: x = init (x) PM ; y = x (x) p0 ; output in log domain.
__global__ void final_kernel(const int* __restrict__ act,
                             const float* __restrict__ init_vec,
                             float* __restrict__ out) {
    int bl = blockIdx.x;
    int b = bl >> 6, l = bl & 63;
    HMat W = latest_h(act, b, l, 6);
    __shared__ float ci[D];
    __shared__ float xw[D];
    int t = threadIdx.x;   // 64
    ci[t] = expf(-init_vec[t]);
    __syncthreads();

    float scq = sc_comp(W.sc, t >> 4);
    float s = 0.f;
#pragma unroll 8
    for (int k = 0; k < D; k++)
        s += frcp(fmaf(scq, __half2float(W.m[k * D + t]), ci[k]));
    xw[t] = frcp(s);
    __syncthreads();

    float s2 = 0.f;
#pragma unroll 8
    for (int k = 0; k < D; k++)
        s2 += frcp(xw[k] + g_p0tab[k * D + t]);
    out[(size_t)bl * D + t] = logf(s2);
}

extern "C" void kernel_launch(void* const* d_in, const int* in_sizes, int n_in,
                              void* d_out, int out_size) {
    const float* p        = (const float*)d_in[0];  // (5, 64, 64)
    const float* init_vec = (const float*)d_in[1];  // (64,)
    const int*   act      = (const int*)d_in[2];    // (8, 64)
    float* out = (float*)d_out;                     // (8, 64, 64)

    exp_tab_kernel<<<5, 256>>>(p);                  // also resets g_ctr
    pairh_kernel<<<64, 256>>>();
    stage2h_kernel<<<1072, 256>>>(act);
    hstep_pk<<<PK_GRID, 256>>>(act, 2, 8 * (L - 4)  * 4);   // -> H_BUF0
    hstep_pk<<<PK_GRID, 256>>>(act, 3, 8 * (L - 8)  * 4);   // -> H_BUF1
    hstep_pk<<<PK_GRID, 256>>>(act, 4, 8 * (L - 16) * 4);   // -> H_BUF0
    hstep_pk<<<PK_GRID, 256>>>(act, 5, 8 * (L - 32) * 4);   // -> H_BUF1
    final_kernel<<<512, 64>>>(act, init_vec, out);
}